// round 10
// baseline (speedup 1.0000x reference)
#include <cuda_runtime.h>
#include <cuda_bf16.h>

#define LMAX 13
#define LPAD 14
#define NP 7          // float2 pairs per padded row (LPAD/2)
#define N_TYPES 20
#define NRES_MAX 2048
#define DV 64
#define TPB 192       // = DV * 3

__constant__ int c_res_len[N_TYPES] = {3,4,5,5,6,6,6,7,7,7,7,7,8,8,8,9,10,10,11,13};
__device__ int g_starts[NRES_MAX];

// padded weights, built once per launch by pad_weights_kernel
__device__ float g_Wpad_atm[N_TYPES * LMAX * DV * LPAD];  // [t][m][v][14], slot13=0
__device__ float g_Wpad_amn[N_TYPES * DV * LPAD];         // [t][v][14],    slot13=0

// ---------------------------------------------------------------------------
// Kernel 0: pad W_atm / W_amn rows 13 -> 14 (zero in slot 13).
// ---------------------------------------------------------------------------
__global__ void pad_weights_kernel(const float* __restrict__ W_amn,
                                   const float* __restrict__ W_atm) {
    const int NATM = N_TYPES * LMAX * DV;       // rows of W_atm
    const int NAMN = N_TYPES * DV;              // rows of W_amn
    int idx = blockIdx.x * blockDim.x + threadIdx.x;
    if (idx < NATM * LPAD) {
        int row = idx / LPAD, l = idx - row * LPAD;
        g_Wpad_atm[idx] = (l < LMAX) ? W_atm[row * LMAX + l] : 0.0f;
    } else {
        int j = idx - NATM * LPAD;
        if (j < NAMN * LPAD) {
            int row = j / LPAD, l = j - row * LPAD;
            g_Wpad_amn[j] = (l < LMAX) ? W_amn[row * LMAX + l] : 0.0f;
        }
    }
}

// ---------------------------------------------------------------------------
// Kernel 1: exclusive scan of residue lengths -> g_starts. One block.
// ---------------------------------------------------------------------------
__global__ void scan_starts_kernel(const int* __restrict__ seq, int n_res) {
    __shared__ int s[1024];
    int tid = threadIdx.x;
    int i0 = 2 * tid, i1 = 2 * tid + 1;
    int l0 = (i0 < n_res) ? c_res_len[seq[i0]] : 0;
    int l1 = (i1 < n_res) ? c_res_len[seq[i1]] : 0;
    int pair = l0 + l1;
    s[tid] = pair;
    __syncthreads();
    #pragma unroll
    for (int off = 1; off < 1024; off <<= 1) {
        int v = (tid >= off) ? s[tid - off] : 0;
        __syncthreads();
        s[tid] += v;
        __syncthreads();
    }
    int excl = s[tid] - pair;
    if (i0 < n_res) g_starts[i0] = excl;
    if (i1 < n_res) g_starts[i1] = excl + l0;
}

// ---------------------------------------------------------------------------
// Templated hot path. Exact trip counts for L; m-loop unrolled x2 with a
// static tail (L is compile-time). Bodies stay small for I$ locality.
// ---------------------------------------------------------------------------
template<int L>
__device__ __forceinline__ void posmix_body(
    const float2* __restrict__ sW2v,   // shared W base for this thread's v
    const float2* __restrict__ sd2d,   // shared diff base for this thread's d
    const float2* __restrict__ gWa2,   // padded W_amn row for (t, v), float2
    float* __restrict__ qamn,
    float* __restrict__ patm,
    int B, int bstride_amn, int bstride_atm)
{
    constexpr int NPL = (L + 1) / 2;   // float2 pairs covering L
    // beyond-L lanes: diff is zero-padded, so real-W x 0 contributions vanish

    #pragma unroll 1
    for (int bb0 = 0; bb0 < B; bb0 += 4) {
        float2 dv0[NPL], dv1[NPL], dv2[NPL], dv3[NPL];
        #pragma unroll
        for (int p = 0; p < NPL; p++) {
            dv0[p] = sd2d[(bb0 + 0) * 3 * NP + p];
            dv1[p] = sd2d[(bb0 + 1) * 3 * NP + p];
            dv2[p] = sd2d[(bb0 + 2) * 3 * NP + p];
            dv3[p] = sd2d[(bb0 + 3) * 3 * NP + p];
        }

        // ---- x_v_amn : vectorized dot against padded W_amn (L1-cached) ----
        {
            float a0 = 0.f, a1 = 0.f, a2 = 0.f, a3 = 0.f;
            #pragma unroll
            for (int p = 0; p < NPL; p++) {
                float2 w = __ldg(&gWa2[p]);
                a0 += w.x * dv0[p].x + w.y * dv0[p].y;
                a1 += w.x * dv1[p].x + w.y * dv1[p].y;
                a2 += w.x * dv2[p].x + w.y * dv2[p].y;
                a3 += w.x * dv3[p].x + w.y * dv3[p].y;
            }
            float* q = qamn + bb0 * bstride_amn;
            q[0] = a0;
            q += bstride_amn; q[0] = a1;
            q += bstride_amn; q[0] = a2;
            q += bstride_amn; q[0] = a3;
        }

        // ---- x_v_atm : m-loop unrolled x2, static tail ----
        float* p0 = patm + bb0 * bstride_atm;
        float* p1 = p0 + bstride_atm;
        float* p2 = p1 + bstride_atm;
        float* p3 = p2 + bstride_atm;
        const float2* wr = sW2v;

        #pragma unroll 1
        for (int m = 0; m < L / 2; m++) {
            float a0 = 0.f, a1 = 0.f, a2 = 0.f, a3 = 0.f;
            float b0 = 0.f, b1 = 0.f, b2 = 0.f, b3 = 0.f;
            #pragma unroll
            for (int p = 0; p < NPL; p++) {
                float2 w = wr[p];
                float2 u = wr[p + DV * NP];
                a0 += w.x * dv0[p].x + w.y * dv0[p].y;
                a1 += w.x * dv1[p].x + w.y * dv1[p].y;
                a2 += w.x * dv2[p].x + w.y * dv2[p].y;
                a3 += w.x * dv3[p].x + w.y * dv3[p].y;
                b0 += u.x * dv0[p].x + u.y * dv0[p].y;
                b1 += u.x * dv1[p].x + u.y * dv1[p].y;
                b2 += u.x * dv2[p].x + u.y * dv2[p].y;
                b3 += u.x * dv3[p].x + u.y * dv3[p].y;
            }
            p0[0] = a0; p0[DV * 3] = b0;
            p1[0] = a1; p1[DV * 3] = b1;
            p2[0] = a2; p2[DV * 3] = b2;
            p3[0] = a3; p3[DV * 3] = b3;
            p0 += 2 * DV * 3; p1 += 2 * DV * 3; p2 += 2 * DV * 3; p3 += 2 * DV * 3;
            wr += 2 * DV * NP;
        }
        if (L & 1) {   // static tail for odd L
            float a0 = 0.f, a1 = 0.f, a2 = 0.f, a3 = 0.f;
            #pragma unroll
            for (int p = 0; p < NPL; p++) {
                float2 w = wr[p];
                a0 += w.x * dv0[p].x + w.y * dv0[p].y;
                a1 += w.x * dv1[p].x + w.y * dv1[p].y;
                a2 += w.x * dv2[p].x + w.y * dv2[p].y;
                a3 += w.x * dv3[p].x + w.y * dv3[p].y;
            }
            p0[0] = a0; p1[0] = a1; p2[0] = a2; p3[0] = a3;
        }
    }
}

// ---------------------------------------------------------------------------
// Kernel 2: fused gather + dual-einsum + scatter. One block per residue.
// ---------------------------------------------------------------------------
__global__ __launch_bounds__(TPB, 4) void posmix_kernel(
    const float* __restrict__ pos_atm,   // (B, atoms, 3)
    const float* __restrict__ pos_amn,   // (B, n_res, 3)
    const int*   __restrict__ seq,       // (n_res,)
    float* __restrict__ out_atm,         // (B, atoms, 64, 3)
    float* __restrict__ out_amn,         // (B, n_res, 64, 3)
    int B, int n_res, int atoms)
{
    extern __shared__ float smem[];
    float* sW    = smem;                        // LMAX*DV*LPAD floats
    float* sdiff = smem + LMAX * DV * LPAD;     // B*3*LPAD floats

    const int i   = blockIdx.x;
    const int tid = threadIdx.x;
    const int t   = seq[i];
    const int L   = c_res_len[t];
    const int start = g_starts[i];

    // --- stage pre-padded W_atm[t][0:L] : straight float4 copy ---
    const float4* gW4 = (const float4*)g_Wpad_atm + (size_t)t * (LMAX * DV * LPAD / 4);
    float4* sW4 = (float4*)sW;
    const int n4 = L * (DV * LPAD / 4);          // L * 224
    for (int idx = tid; idx < n4; idx += TPB) sW4[idx] = gW4[idx];

    // --- stage diffs, layout [b][d][LPAD], zero-padded in l ---
    const int nd = B * 3 * LPAD;
    for (int idx = tid; idx < nd; idx += TPB) {
        int b = idx / (3 * LPAD);
        int r = idx - b * (3 * LPAD);
        int d = r / LPAD;
        int l = r - d * LPAD;
        float val = 0.0f;
        if (l < L) {
            val = pos_atm[((size_t)b * atoms + start + l) * 3 + d]
                - pos_amn[((size_t)b * n_res + i) * 3 + d];
        }
        sdiff[idx] = val;
    }
    __syncthreads();

    const int v = tid / 3;
    const int d = tid - v * 3;
    const float2* sW2v = (const float2*)sW + v * NP;
    const float2* sd2d = (const float2*)sdiff + d * NP;
    const float2* gWa2 = (const float2*)g_Wpad_amn + ((size_t)t * DV + v) * NP;

    const int bstride_atm = atoms * (DV * 3);
    const int bstride_amn = n_res * (DV * 3);

    float* qamn = out_amn + i * (DV * 3) + tid;
    float* patm = out_atm + start * (DV * 3) + tid;

    switch (L) {
        case 3:  posmix_body<3> (sW2v, sd2d, gWa2, qamn, patm, B, bstride_amn, bstride_atm); break;
        case 4:  posmix_body<4> (sW2v, sd2d, gWa2, qamn, patm, B, bstride_amn, bstride_atm); break;
        case 5:  posmix_body<5> (sW2v, sd2d, gWa2, qamn, patm, B, bstride_amn, bstride_atm); break;
        case 6:  posmix_body<6> (sW2v, sd2d, gWa2, qamn, patm, B, bstride_amn, bstride_atm); break;
        case 7:  posmix_body<7> (sW2v, sd2d, gWa2, qamn, patm, B, bstride_amn, bstride_atm); break;
        case 8:  posmix_body<8> (sW2v, sd2d, gWa2, qamn, patm, B, bstride_amn, bstride_atm); break;
        case 9:  posmix_body<9> (sW2v, sd2d, gWa2, qamn, patm, B, bstride_amn, bstride_atm); break;
        case 10: posmix_body<10>(sW2v, sd2d, gWa2, qamn, patm, B, bstride_amn, bstride_atm); break;
        case 11: posmix_body<11>(sW2v, sd2d, gWa2, qamn, patm, B, bstride_amn, bstride_atm); break;
        default: posmix_body<13>(sW2v, sd2d, gWa2, qamn, patm, B, bstride_amn, bstride_atm); break;
    }
}

// ---------------------------------------------------------------------------
// Launch: d_out = concat(x_v_atm.ravel(), x_v_amn.ravel())
// ---------------------------------------------------------------------------
extern "C" void kernel_launch(void* const* d_in, const int* in_sizes, int n_in,
                              void* d_out, int out_size) {
    const float* pos_atm = (const float*)d_in[0];
    const float* pos_amn = (const float*)d_in[1];
    const float* W_amn   = (const float*)d_in[2];
    const float* W_atm   = (const float*)d_in[3];
    const int*   seq     = (const int*)d_in[4];

    const int n_res = in_sizes[4];                  // 2048
    const int B     = in_sizes[1] / (n_res * 3);    // 16
    const int atoms = in_sizes[0] / (B * 3);        // 15036

    float* out_atm = (float*)d_out;
    float* out_amn = out_atm + (size_t)B * atoms * DV * 3;

    const int smem_bytes = (LMAX * DV * LPAD + 16 * 3 * LPAD) * (int)sizeof(float);
    cudaFuncSetAttribute(posmix_kernel,
                         cudaFuncAttributeMaxDynamicSharedMemorySize, smem_bytes);

    const int npad = (N_TYPES * LMAX * DV + N_TYPES * DV) * LPAD;
    pad_weights_kernel<<<(npad + 255) / 256, 256>>>(W_amn, W_atm);
    scan_starts_kernel<<<1, 1024>>>(seq, n_res);
    posmix_kernel<<<n_res, TPB, smem_bytes>>>(pos_atm, pos_amn, seq,
                                              out_atm, out_amn, B, n_res, atoms);
}

// round 12
// speedup vs baseline: 1.2417x; 1.2417x over previous
#include <cuda_runtime.h>
#include <cuda_bf16.h>

#define LMAX 13
#define LPAD 14
#define NP 7          // float2 pairs per padded row (LPAD/2)
#define N_TYPES 20
#define NRES_MAX 2048
#define DV 64
#define TPB 192       // = DV * 3

__constant__ int c_res_len[N_TYPES] = {3,4,5,5,6,6,6,7,7,7,7,7,8,8,8,9,10,10,11,13};
__device__ int g_starts[NRES_MAX];

// padded weights, built once per launch by prep_kernel
__device__ float g_Wpad_atm[N_TYPES * LMAX * DV * LPAD];  // [t][m][v][14], slot13=0
__device__ float g_Wpad_amn[N_TYPES * DV * LPAD];         // [t][v][14],    slot13=0

// ---------------------------------------------------------------------------
// Kernel 0: fused prep. Block 0: exclusive scan of residue lengths.
// Blocks 1..: pad W_atm / W_amn rows 13 -> 14 (zero slot 13).
// ---------------------------------------------------------------------------
__global__ __launch_bounds__(1024) void prep_kernel(
    const int* __restrict__ seq, int n_res,
    const float* __restrict__ W_amn, const float* __restrict__ W_atm)
{
    if (blockIdx.x == 0) {
        __shared__ int s[1024];
        int tid = threadIdx.x;
        int i0 = 2 * tid, i1 = 2 * tid + 1;
        int l0 = (i0 < n_res) ? c_res_len[seq[i0]] : 0;
        int l1 = (i1 < n_res) ? c_res_len[seq[i1]] : 0;
        int pair = l0 + l1;
        s[tid] = pair;
        __syncthreads();
        #pragma unroll
        for (int off = 1; off < 1024; off <<= 1) {
            int v = (tid >= off) ? s[tid - off] : 0;
            __syncthreads();
            s[tid] += v;
            __syncthreads();
        }
        int excl = s[tid] - pair;
        if (i0 < n_res) g_starts[i0] = excl;
        if (i1 < n_res) g_starts[i1] = excl + l0;
    } else {
        const int NATM = N_TYPES * LMAX * DV;   // W_atm rows
        const int NAMN = N_TYPES * DV;          // W_amn rows
        int idx = (blockIdx.x - 1) * 1024 + threadIdx.x;
        if (idx < NATM * LPAD) {
            int row = idx / LPAD, l = idx - row * LPAD;
            g_Wpad_atm[idx] = (l < LMAX) ? W_atm[row * LMAX + l] : 0.0f;
        } else {
            int j = idx - NATM * LPAD;
            if (j < NAMN * LPAD) {
                int row = j / LPAD, l = j - row * LPAD;
                g_Wpad_amn[j] = (l < LMAX) ? W_amn[row * LMAX + l] : 0.0f;
            }
        }
    }
}

// ---------------------------------------------------------------------------
// Templated hot path — R8 structure (single-m dynamic loop, 4 accumulators,
// tiny body for I$ locality), with the amn dot vectorized via padded W_amn.
// ---------------------------------------------------------------------------
template<int L>
__device__ __forceinline__ void posmix_body(
    const float2* __restrict__ sW2v,   // shared W base for this thread's v
    const float2* __restrict__ sd2d,   // shared diff base for this thread's d
    const float2* __restrict__ gWa2,   // padded W_amn row for (t, v), float2
    float* __restrict__ qamn,
    float* __restrict__ patm,
    int B, int bstride_amn, int bstride_atm)
{
    constexpr int NPL = (L + 1) / 2;   // float2 pairs covering L
    // beyond-L lanes: diff is zero-padded, so W x 0 contributions vanish

    #pragma unroll 1
    for (int bb0 = 0; bb0 < B; bb0 += 4) {
        float2 dv0[NPL], dv1[NPL], dv2[NPL], dv3[NPL];
        #pragma unroll
        for (int p = 0; p < NPL; p++) {
            dv0[p] = sd2d[(bb0 + 0) * 3 * NP + p];
            dv1[p] = sd2d[(bb0 + 1) * 3 * NP + p];
            dv2[p] = sd2d[(bb0 + 2) * 3 * NP + p];
            dv3[p] = sd2d[(bb0 + 3) * 3 * NP + p];
        }

        // ---- x_v_amn : vectorized dot against padded W_amn (L1-cached) ----
        {
            float a0 = 0.f, a1 = 0.f, a2 = 0.f, a3 = 0.f;
            #pragma unroll
            for (int p = 0; p < NPL; p++) {
                float2 w = __ldg(&gWa2[p]);
                a0 += w.x * dv0[p].x + w.y * dv0[p].y;
                a1 += w.x * dv1[p].x + w.y * dv1[p].y;
                a2 += w.x * dv2[p].x + w.y * dv2[p].y;
                a3 += w.x * dv3[p].x + w.y * dv3[p].y;
            }
            float* q = qamn + bb0 * bstride_amn;
            q[0] = a0;
            q += bstride_amn; q[0] = a1;
            q += bstride_amn; q[0] = a2;
            q += bstride_amn; q[0] = a3;
        }

        // ---- x_v_atm : dynamic m-loop (tiny body, loops L times) ----
        float* p0 = patm + bb0 * bstride_atm;
        float* p1 = p0 + bstride_atm;
        float* p2 = p1 + bstride_atm;
        float* p3 = p2 + bstride_atm;
        const float2* wr = sW2v;
        #pragma unroll 1
        for (int m = 0; m < L; m++) {
            float a0 = 0.f, a1 = 0.f, a2 = 0.f, a3 = 0.f;
            #pragma unroll
            for (int p = 0; p < NPL; p++) {
                float2 w = wr[p];
                a0 += w.x * dv0[p].x + w.y * dv0[p].y;
                a1 += w.x * dv1[p].x + w.y * dv1[p].y;
                a2 += w.x * dv2[p].x + w.y * dv2[p].y;
                a3 += w.x * dv3[p].x + w.y * dv3[p].y;
            }
            p0[0] = a0; p1[0] = a1; p2[0] = a2; p3[0] = a3;
            p0 += DV * 3; p1 += DV * 3; p2 += DV * 3; p3 += DV * 3;
            wr += DV * NP;
        }
    }
}

// ---------------------------------------------------------------------------
// Kernel 2: fused gather + dual-einsum + scatter. One block per residue.
// ---------------------------------------------------------------------------
__global__ __launch_bounds__(TPB, 4) void posmix_kernel(
    const float* __restrict__ pos_atm,   // (B, atoms, 3)
    const float* __restrict__ pos_amn,   // (B, n_res, 3)
    const int*   __restrict__ seq,       // (n_res,)
    float* __restrict__ out_atm,         // (B, atoms, 64, 3)
    float* __restrict__ out_amn,         // (B, n_res, 64, 3)
    int B, int n_res, int atoms)
{
    extern __shared__ float smem[];
    float* sW    = smem;                        // LMAX*DV*LPAD floats
    float* sdiff = smem + LMAX * DV * LPAD;     // B*3*LPAD floats

    const int i   = blockIdx.x;
    const int tid = threadIdx.x;
    const int t   = seq[i];
    const int L   = c_res_len[t];
    const int start = g_starts[i];

    // --- stage pre-padded W_atm[t][0:L] : straight float4 copy ---
    const float4* gW4 = (const float4*)g_Wpad_atm + (size_t)t * (LMAX * DV * LPAD / 4);
    float4* sW4 = (float4*)sW;
    const int n4 = L * (DV * LPAD / 4);          // L * 224
    for (int idx = tid; idx < n4; idx += TPB) sW4[idx] = gW4[idx];

    // --- stage diffs, layout [b][d][LPAD], zero-padded in l ---
    const int nd = B * 3 * LPAD;
    for (int idx = tid; idx < nd; idx += TPB) {
        int b = idx / (3 * LPAD);
        int r = idx - b * (3 * LPAD);
        int d = r / LPAD;
        int l = r - d * LPAD;
        float val = 0.0f;
        if (l < L) {
            val = pos_atm[((size_t)b * atoms + start + l) * 3 + d]
                - pos_amn[((size_t)b * n_res + i) * 3 + d];
        }
        sdiff[idx] = val;
    }
    __syncthreads();

    const int v = tid / 3;
    const int d = tid - v * 3;
    const float2* sW2v = (const float2*)sW + v * NP;
    const float2* sd2d = (const float2*)sdiff + d * NP;
    const float2* gWa2 = (const float2*)g_Wpad_amn + ((size_t)t * DV + v) * NP;

    const int bstride_atm = atoms * (DV * 3);
    const int bstride_amn = n_res * (DV * 3);

    float* qamn = out_amn + i * (DV * 3) + tid;
    float* patm = out_atm + start * (DV * 3) + tid;

    switch (L) {
        case 3:  posmix_body<3> (sW2v, sd2d, gWa2, qamn, patm, B, bstride_amn, bstride_atm); break;
        case 4:  posmix_body<4> (sW2v, sd2d, gWa2, qamn, patm, B, bstride_amn, bstride_atm); break;
        case 5:  posmix_body<5> (sW2v, sd2d, gWa2, qamn, patm, B, bstride_amn, bstride_atm); break;
        case 6:  posmix_body<6> (sW2v, sd2d, gWa2, qamn, patm, B, bstride_amn, bstride_atm); break;
        case 7:  posmix_body<7> (sW2v, sd2d, gWa2, qamn, patm, B, bstride_amn, bstride_atm); break;
        case 8:  posmix_body<8> (sW2v, sd2d, gWa2, qamn, patm, B, bstride_amn, bstride_atm); break;
        case 9:  posmix_body<9> (sW2v, sd2d, gWa2, qamn, patm, B, bstride_amn, bstride_atm); break;
        case 10: posmix_body<10>(sW2v, sd2d, gWa2, qamn, patm, B, bstride_amn, bstride_atm); break;
        case 11: posmix_body<11>(sW2v, sd2d, gWa2, qamn, patm, B, bstride_amn, bstride_atm); break;
        default: posmix_body<13>(sW2v, sd2d, gWa2, qamn, patm, B, bstride_amn, bstride_atm); break;
    }
}

// ---------------------------------------------------------------------------
// Launch: d_out = concat(x_v_atm.ravel(), x_v_amn.ravel())
// ---------------------------------------------------------------------------
extern "C" void kernel_launch(void* const* d_in, const int* in_sizes, int n_in,
                              void* d_out, int out_size) {
    const float* pos_atm = (const float*)d_in[0];
    const float* pos_amn = (const float*)d_in[1];
    const float* W_amn   = (const float*)d_in[2];
    const float* W_atm   = (const float*)d_in[3];
    const int*   seq     = (const int*)d_in[4];

    const int n_res = in_sizes[4];                  // 2048
    const int B     = in_sizes[1] / (n_res * 3);    // 16
    const int atoms = in_sizes[0] / (B * 3);        // 15036

    float* out_atm = (float*)d_out;
    float* out_amn = out_atm + (size_t)B * atoms * DV * 3;

    const int smem_bytes = (LMAX * DV * LPAD + 16 * 3 * LPAD) * (int)sizeof(float);
    cudaFuncSetAttribute(posmix_kernel,
                         cudaFuncAttributeMaxDynamicSharedMemorySize, smem_bytes);

    const int npad = (N_TYPES * LMAX * DV + N_TYPES * DV) * LPAD;   // 246,400
    const int prep_blocks = 1 + (npad + 1023) / 1024;               // scan + pad
    prep_kernel<<<prep_blocks, 1024>>>(seq, n_res, W_amn, W_atm);
    posmix_kernel<<<n_res, TPB, smem_bytes>>>(pos_atm, pos_amn, seq,
                                              out_atm, out_amn, B, n_res, atoms);
}

// round 13
// speedup vs baseline: 1.3537x; 1.0902x over previous
#include <cuda_runtime.h>
#include <cuda_bf16.h>

#define LMAX 13
#define LPAD 14
#define NP 7          // float2 pairs per padded row (LPAD/2)
#define N_TYPES 20
#define NRES_MAX 2048
#define DV 64
#define TPB 192       // = DV * 3

typedef unsigned long long u64;

// packed f32x2 fma: acc = w * dv + acc   (2 scalar FMAs in 1 issue slot)
#define FMA2(acc, w, dv) \
    asm("fma.rn.f32x2 %0, %1, %2, %3;" : "=l"(acc) : "l"(w), "l"(dv), "l"(acc))

// horizontal sum of a packed f32x2
__device__ __forceinline__ float hsum2(u64 v) {
    float lo, hi;
    asm("mov.b64 {%0, %1}, %2;" : "=f"(lo), "=f"(hi) : "l"(v));
    return lo + hi;
}

__constant__ int c_res_len[N_TYPES] = {3,4,5,5,6,6,6,7,7,7,7,7,8,8,8,9,10,10,11,13};
__device__ int g_starts[NRES_MAX];

// padded weights, built once per launch by prep_kernel
__device__ float g_Wpad_atm[N_TYPES * LMAX * DV * LPAD];  // [t][m][v][14], slot13=0
__device__ float g_Wpad_amn[N_TYPES * DV * LPAD];         // [t][v][14],    slot13=0

// ---------------------------------------------------------------------------
// Kernel 0: fused prep. Block 0: exclusive scan of residue lengths.
// Blocks 1..: pad W_atm / W_amn rows 13 -> 14 (zero slot 13).
// ---------------------------------------------------------------------------
__global__ __launch_bounds__(1024) void prep_kernel(
    const int* __restrict__ seq, int n_res,
    const float* __restrict__ W_amn, const float* __restrict__ W_atm)
{
    if (blockIdx.x == 0) {
        __shared__ int s[1024];
        int tid = threadIdx.x;
        int i0 = 2 * tid, i1 = 2 * tid + 1;
        int l0 = (i0 < n_res) ? c_res_len[seq[i0]] : 0;
        int l1 = (i1 < n_res) ? c_res_len[seq[i1]] : 0;
        int pair = l0 + l1;
        s[tid] = pair;
        __syncthreads();
        #pragma unroll
        for (int off = 1; off < 1024; off <<= 1) {
            int v = (tid >= off) ? s[tid - off] : 0;
            __syncthreads();
            s[tid] += v;
            __syncthreads();
        }
        int excl = s[tid] - pair;
        if (i0 < n_res) g_starts[i0] = excl;
        if (i1 < n_res) g_starts[i1] = excl + l0;
    } else {
        const int NATM = N_TYPES * LMAX * DV;   // W_atm rows
        const int NAMN = N_TYPES * DV;          // W_amn rows
        int idx = (blockIdx.x - 1) * 1024 + threadIdx.x;
        if (idx < NATM * LPAD) {
            int row = idx / LPAD, l = idx - row * LPAD;
            g_Wpad_atm[idx] = (l < LMAX) ? W_atm[row * LMAX + l] : 0.0f;
        } else {
            int j = idx - NATM * LPAD;
            if (j < NAMN * LPAD) {
                int row = j / LPAD, l = j - row * LPAD;
                g_Wpad_amn[j] = (l < LMAX) ? W_amn[row * LMAX + l] : 0.0f;
            }
        }
    }
}

// ---------------------------------------------------------------------------
// Templated hot path — R12 structure (single-m dynamic loop, tiny body),
// with all dot products done via packed fma.rn.f32x2 (2 FMAs / issue slot).
// ---------------------------------------------------------------------------
template<int L>
__device__ __forceinline__ void posmix_body(
    const u64* __restrict__ sW64v,     // shared W base for this thread's v (f32x2)
    const u64* __restrict__ sd64d,     // shared diff base for this thread's d (f32x2)
    const u64* __restrict__ gWa64,     // padded W_amn row for (t, v) (f32x2)
    float* __restrict__ qamn,
    float* __restrict__ patm,
    int B, int bstride_amn, int bstride_atm)
{
    constexpr int NPL = (L + 1) / 2;   // f32x2 pairs covering L
    // beyond-L lanes: diff is zero-padded, so W x 0 contributions vanish

    #pragma unroll 1
    for (int bb0 = 0; bb0 < B; bb0 += 4) {
        u64 dv0[NPL], dv1[NPL], dv2[NPL], dv3[NPL];
        #pragma unroll
        for (int p = 0; p < NPL; p++) {
            dv0[p] = sd64d[(bb0 + 0) * 3 * NP + p];
            dv1[p] = sd64d[(bb0 + 1) * 3 * NP + p];
            dv2[p] = sd64d[(bb0 + 2) * 3 * NP + p];
            dv3[p] = sd64d[(bb0 + 3) * 3 * NP + p];
        }

        // ---- x_v_amn : packed dot against padded W_amn ----
        {
            u64 c0 = 0, c1 = 0, c2 = 0, c3 = 0;
            #pragma unroll
            for (int p = 0; p < NPL; p++) {
                u64 w = gWa64[p];
                FMA2(c0, w, dv0[p]);
                FMA2(c1, w, dv1[p]);
                FMA2(c2, w, dv2[p]);
                FMA2(c3, w, dv3[p]);
            }
            float* q = qamn + bb0 * bstride_amn;
            q[0] = hsum2(c0);
            q += bstride_amn; q[0] = hsum2(c1);
            q += bstride_amn; q[0] = hsum2(c2);
            q += bstride_amn; q[0] = hsum2(c3);
        }

        // ---- x_v_atm : dynamic m-loop (tiny body, loops L times) ----
        float* p0 = patm + bb0 * bstride_atm;
        float* p1 = p0 + bstride_atm;
        float* p2 = p1 + bstride_atm;
        float* p3 = p2 + bstride_atm;
        const u64* wr = sW64v;
        #pragma unroll 1
        for (int m = 0; m < L; m++) {
            u64 c0 = 0, c1 = 0, c2 = 0, c3 = 0;
            #pragma unroll
            for (int p = 0; p < NPL; p++) {
                u64 w = wr[p];
                FMA2(c0, w, dv0[p]);
                FMA2(c1, w, dv1[p]);
                FMA2(c2, w, dv2[p]);
                FMA2(c3, w, dv3[p]);
            }
            p0[0] = hsum2(c0); p1[0] = hsum2(c1);
            p2[0] = hsum2(c2); p3[0] = hsum2(c3);
            p0 += DV * 3; p1 += DV * 3; p2 += DV * 3; p3 += DV * 3;
            wr += DV * NP;
        }
    }
}

// ---------------------------------------------------------------------------
// Kernel 2: fused gather + dual-einsum + scatter. One block per residue.
// ---------------------------------------------------------------------------
__global__ __launch_bounds__(TPB, 4) void posmix_kernel(
    const float* __restrict__ pos_atm,   // (B, atoms, 3)
    const float* __restrict__ pos_amn,   // (B, n_res, 3)
    const int*   __restrict__ seq,       // (n_res,)
    float* __restrict__ out_atm,         // (B, atoms, 64, 3)
    float* __restrict__ out_amn,         // (B, n_res, 64, 3)
    int B, int n_res, int atoms)
{
    extern __shared__ float smem[];
    float* sW    = smem;                        // LMAX*DV*LPAD floats
    float* sdiff = smem + LMAX * DV * LPAD;     // B*3*LPAD floats

    const int i   = blockIdx.x;
    const int tid = threadIdx.x;
    const int t   = seq[i];
    const int L   = c_res_len[t];
    const int start = g_starts[i];

    // --- stage pre-padded W_atm[t][0:L] : straight float4 copy ---
    const float4* gW4 = (const float4*)g_Wpad_atm + (size_t)t * (LMAX * DV * LPAD / 4);
    float4* sW4 = (float4*)sW;
    const int n4 = L * (DV * LPAD / 4);          // L * 224
    for (int idx = tid; idx < n4; idx += TPB) sW4[idx] = gW4[idx];

    // --- stage diffs, layout [b][d][LPAD], zero-padded in l ---
    const int nd = B * 3 * LPAD;
    for (int idx = tid; idx < nd; idx += TPB) {
        int b = idx / (3 * LPAD);
        int r = idx - b * (3 * LPAD);
        int d = r / LPAD;
        int l = r - d * LPAD;
        float val = 0.0f;
        if (l < L) {
            val = pos_atm[((size_t)b * atoms + start + l) * 3 + d]
                - pos_amn[((size_t)b * n_res + i) * 3 + d];
        }
        sdiff[idx] = val;
    }
    __syncthreads();

    const int v = tid / 3;
    const int d = tid - v * 3;
    const u64* sW64v = (const u64*)sW + v * NP;
    const u64* sd64d = (const u64*)sdiff + d * NP;
    const u64* gWa64 = (const u64*)g_Wpad_amn + ((size_t)t * DV + v) * NP;

    const int bstride_atm = atoms * (DV * 3);
    const int bstride_amn = n_res * (DV * 3);

    float* qamn = out_amn + i * (DV * 3) + tid;
    float* patm = out_atm + start * (DV * 3) + tid;

    switch (L) {
        case 3:  posmix_body<3> (sW64v, sd64d, gWa64, qamn, patm, B, bstride_amn, bstride_atm); break;
        case 4:  posmix_body<4> (sW64v, sd64d, gWa64, qamn, patm, B, bstride_amn, bstride_atm); break;
        case 5:  posmix_body<5> (sW64v, sd64d, gWa64, qamn, patm, B, bstride_amn, bstride_atm); break;
        case 6:  posmix_body<6> (sW64v, sd64d, gWa64, qamn, patm, B, bstride_amn, bstride_atm); break;
        case 7:  posmix_body<7> (sW64v, sd64d, gWa64, qamn, patm, B, bstride_amn, bstride_atm); break;
        case 8:  posmix_body<8> (sW64v, sd64d, gWa64, qamn, patm, B, bstride_amn, bstride_atm); break;
        case 9:  posmix_body<9> (sW64v, sd64d, gWa64, qamn, patm, B, bstride_amn, bstride_atm); break;
        case 10: posmix_body<10>(sW64v, sd64d, gWa64, qamn, patm, B, bstride_amn, bstride_atm); break;
        case 11: posmix_body<11>(sW64v, sd64d, gWa64, qamn, patm, B, bstride_amn, bstride_atm); break;
        default: posmix_body<13>(sW64v, sd64d, gWa64, qamn, patm, B, bstride_amn, bstride_atm); break;
    }
}

// ---------------------------------------------------------------------------
// Launch: d_out = concat(x_v_atm.ravel(), x_v_amn.ravel())
// ---------------------------------------------------------------------------
extern "C" void kernel_launch(void* const* d_in, const int* in_sizes, int n_in,
                              void* d_out, int out_size) {
    const float* pos_atm = (const float*)d_in[0];
    const float* pos_amn = (const float*)d_in[1];
    const float* W_amn   = (const float*)d_in[2];
    const float* W_atm   = (const float*)d_in[3];
    const int*   seq     = (const int*)d_in[4];

    const int n_res = in_sizes[4];                  // 2048
    const int B     = in_sizes[1] / (n_res * 3);    // 16
    const int atoms = in_sizes[0] / (B * 3);        // 15036

    float* out_atm = (float*)d_out;
    float* out_amn = out_atm + (size_t)B * atoms * DV * 3;

    const int smem_bytes = (LMAX * DV * LPAD + 16 * 3 * LPAD) * (int)sizeof(float);
    cudaFuncSetAttribute(posmix_kernel,
                         cudaFuncAttributeMaxDynamicSharedMemorySize, smem_bytes);

    const int npad = (N_TYPES * LMAX * DV + N_TYPES * DV) * LPAD;   // 246,400
    const int prep_blocks = 1 + (npad + 1023) / 1024;               // scan + pad
    prep_kernel<<<prep_blocks, 1024>>>(seq, n_res, W_amn, W_atm);
    posmix_kernel<<<n_res, TPB, smem_bytes>>>(pos_atm, pos_amn, seq,
                                              out_atm, out_amn, B, n_res, atoms);
}